// round 6
// baseline (speedup 1.0000x reference)
#include <cuda_runtime.h>
#include <math.h>

// ---------------- constants ----------------
#define VOX   2097152          // 128^3
#define CCH   48               // feature channels
#define NPOS  4736             // 4096 + 512 + 128(pad) positions per batch
#define NGRAM 1078             // 2*528 + 2*10 + 2*1 gram tiles
#define NDICE 2048

// ---------------- device scratch ----------------
__device__ float g_dpart[NDICE * 9];      // dice per-block partials
__device__ float g_gpart[NGRAM * 9];      // gram per-block partials
__device__ float g_fnorm[2 * NPOS * CCH];
__device__ int   g_cls[2 * NPOS];

// ================= kernel A: fused dice + prep =================
__global__ void __launch_bounds__(256)
diceprep_kernel(const float* __restrict__ pred, const int* __restrict__ tgt,
                const float* __restrict__ f0, const float* __restrict__ f1,
                const float* __restrict__ f2) {
    int bid = blockIdx.x;
    if (bid < NDICE) {
        // ---- dice block ----
        const int b = bid >> 10;
        const int chunk = bid & 1023;
        const int Q = VOX / 4;
        float fi0 = 0.f, fi1 = 0.f, fi2 = 0.f;
        float fp0 = 0.f, fp1 = 0.f, fp2 = 0.f;
        float fc0 = 0.f, fc1 = 0.f, fc2 = 0.f;
        const float4* P  = (const float4*)pred;
        const int4*   T4 = (const int4*)tgt;

        for (int q = chunk * 256 + threadIdx.x; q < Q; q += 1024 * 256) {
            float4 x0 = P[(size_t)(b * 3 + 0) * Q + q];
            float4 x1 = P[(size_t)(b * 3 + 1) * Q + q];
            float4 x2 = P[(size_t)(b * 3 + 2) * Q + q];
            int4   tv = T4[(size_t)b * Q + q];

            // inputs ~N(0,1): exp is safe in f32 without max-subtraction
#define DO_VOXEL(pa, pb, pc, tt)                                           \
            {                                                              \
                float e0 = __expf(pa);                                     \
                float e1 = __expf(pb);                                     \
                float e2 = __expf(pc);                                     \
                float inv = __fdividef(1.f, e0 + e1 + e2);                 \
                e0 *= inv; e1 *= inv; e2 *= inv;                           \
                fp0 += e0; fp1 += e1; fp2 += e2;                           \
                int tc = (tt) < 0 ? 0 : (tt);                              \
                if (tc == 0)      { fi0 += e0; fc0 += 1.f; }               \
                else if (tc == 1) { fi1 += e1; fc1 += 1.f; }               \
                else              { fi2 += e2; fc2 += 1.f; }               \
            }
            DO_VOXEL(x0.x, x1.x, x2.x, tv.x);
            DO_VOXEL(x0.y, x1.y, x2.y, tv.y);
            DO_VOXEL(x0.z, x1.z, x2.z, tv.z);
            DO_VOXEL(x0.w, x1.w, x2.w, tv.w);
#undef DO_VOXEL
        }

        float v[9] = { fi0, fi1, fi2, fp0, fp1, fp2, fc0, fc1, fc2 };
#pragma unroll
        for (int o = 16; o; o >>= 1)
#pragma unroll
            for (int q = 0; q < 9; q++)
                v[q] += __shfl_down_sync(0xffffffffu, v[q], o);

        __shared__ float red[8][9];
        int w = threadIdx.x >> 5, l = threadIdx.x & 31;
        if (l == 0)
#pragma unroll
            for (int q = 0; q < 9; q++) red[w][q] = v[q];
        __syncthreads();
        if (threadIdx.x < 9) {
            float s = 0.f;
#pragma unroll
            for (int w2 = 0; w2 < 8; w2++) s += red[w2][threadIdx.x];
            g_dpart[bid * 9 + threadIdx.x] = s;
        }
    } else {
        // ---- prep block ----
        int gid = (bid - NDICE) * 256 + threadIdx.x;
        if (gid >= 2 * NPOS) return;
        int b = gid / NPOS, idx = gid % NPOS;
        const float* fmap;
        int D, s, N, n;
        if (idx < 4096)      { fmap = f0; D = 16; s = 8;  N = 4096; n = idx; }
        else if (idx < 4608) { fmap = f1; D = 8;  s = 16; N = 512;  n = idx - 4096; }
        else                 { fmap = f2; D = 4;  s = 32; N = 64;   n = idx - 4608; }

        float4* dst = (float4*)(g_fnorm + (size_t)gid * CCH);
        if (n >= N) {
            float4 z = make_float4(0.f, 0.f, 0.f, 0.f);
#pragma unroll
            for (int c = 0; c < CCH / 4; c++) dst[c] = z;
            g_cls[gid] = 3;
            return;
        }
        int z = n / (D * D), y = (n / D) % D, x = n % D;
        int tv = tgt[(size_t)b * VOX + ((size_t)(z * s) * 128 + y * s) * 128 + x * s];
        int cls = tv < 0 ? 0 : (tv > 2 ? 2 : tv);
        g_cls[gid] = cls;

        float v[CCH];
        float ss = 0.f;
#pragma unroll
        for (int c = 0; c < CCH; c++) {
            v[c] = fmap[((size_t)b * CCH + c) * N + n];
            ss = fmaf(v[c], v[c], ss);
        }
        float inv = 1.f / fmaxf(sqrtf(ss), 1e-12f);
#pragma unroll
        for (int c = 0; c < CCH / 4; c++)
            dst[c] = make_float4(v[4 * c] * inv, v[4 * c + 1] * inv,
                                 v[4 * c + 2] * inv, v[4 * c + 3] * inv);
    }
}

// ---------------- helpers ----------------
__device__ __forceinline__ void ffma2(unsigned long long& d,
                                      unsigned long long a,
                                      unsigned long long b) {
    asm("fma.rn.f32x2 %0, %1, %2, %0;" : "+l"(d) : "l"(a), "l"(b));
}
__device__ __forceinline__ float ex2f(float x) {
    float y;
    asm("ex2.approx.f32 %0, %1;" : "=f"(y) : "f"(x));
    return y;
}

// ================= kernel B: gram, f32x2 FMA, 512 thr, 8x4 microtile ======
#define BSTRIDE 50
__global__ void __launch_bounds__(512, 1)
gram_kernel() {
    int gid = blockIdx.x;
    int b, p, T, off;
    if (gid < 1056)      { b = gid / 528;  p = gid % 528; T = 32; off = 0; }
    else if (gid < 1076) { int l = gid - 1056; b = l / 10; p = l % 10; T = 4; off = 4096; }
    else                 { b = gid - 1076; p = 0; T = 1; off = 4608; }
    int by = 0;
    while (p >= T - by) { p -= T - by; by++; }
    int bx = by + p;

    extern __shared__ float sm[];
    float* As = sm;                          // [128][48]
    float* Bs = sm + 128 * 48;               // [128][BSTRIDE]
    float* wr = Bs + 128 * BSTRIDE;          // [3][128]
    float* wc = wr + 3 * 128;                // [3][128]

    int tid = threadIdx.x;
    const float4*  FR4 = (const float4*)(g_fnorm + ((size_t)b * NPOS + off + by * 128) * CCH);
    const float2*  FC2 = (const float2*)(g_fnorm + ((size_t)b * NPOS + off + bx * 128) * CCH);

    for (int t = tid; t < 128 * 12; t += 512)
        ((float4*)As)[t] = FR4[t];
    // B rows are 200B (not 16B-aligned) -> float2 stores
    for (int t = tid; t < 128 * 24; t += 512) {
        int r = t / 24, kq = t % 24;
        *(float2*)(Bs + r * BSTRIDE + kq * 2) = FC2[t];
    }
    if (tid < 128) {
        int cr = g_cls[b * NPOS + off + by * 128 + tid];
        wr[tid]       = (cr == 0) ? 1.f : 0.f;
        wr[128 + tid] = (cr == 1) ? 1.f : 0.f;
        wr[256 + tid] = (cr == 2) ? 1.f : 0.f;
    } else if (tid < 256) {
        int t2 = tid - 128;
        int cc = g_cls[b * NPOS + off + bx * 128 + t2];
        wc[t2]       = (cc == 0) ? 1.f : 0.f;
        wc[128 + t2] = (cc == 1) ? 1.f : 0.f;
        wc[256 + t2] = (cc == 2) ? 1.f : 0.f;
    }
    __syncthreads();

    int tx = tid & 31;       // col thread: cols c = tx + j*32, j=0..3
    int ty = tid >> 5;       // row thread: rows r = ty + i*16, i=0..7

    unsigned long long acc[8][4];
#pragma unroll
    for (int i = 0; i < 8; i++)
#pragma unroll
        for (int j = 0; j < 4; j++) acc[i][j] = 0ull;

#pragma unroll 1
    for (int k = 0; k < CCH; k += 2) {
        unsigned long long a2[8], b2[4];
#pragma unroll
        for (int i = 0; i < 8; i++)     // broadcast within warp (ty uniform)
            a2[i] = *(const unsigned long long*)(As + (ty + i * 16) * 48 + k);
#pragma unroll
        for (int j = 0; j < 4; j++)     // conflict-free: lane*18 mod 32 distinct
            b2[j] = *(const unsigned long long*)(Bs + (tx + j * 32) * BSTRIDE + k);
#pragma unroll
        for (int i = 0; i < 8; i++)
#pragma unroll
            for (int j = 0; j < 4; j++) ffma2(acc[i][j], a2[i], b2[j]);
    }

    float lacc[9];
#pragma unroll
    for (int q = 0; q < 9; q++) lacc[q] = 0.f;

    bool diag = (by == bx);
#pragma unroll
    for (int i = 0; i < 8; i++) {
        int rl = ty + i * 16;
        float w0r = wr[rl], w1r = wr[128 + rl], w2r = wr[256 + rl];
        float rs0 = 0.f, rs1 = 0.f, rs2 = 0.f;
#pragma unroll
        for (int j = 0; j < 4; j++) {
            int ml = tx + j * 32;
            unsigned long long u = acc[i][j];
            float lo = __uint_as_float((unsigned)(u & 0xffffffffu));
            float hi = __uint_as_float((unsigned)(u >> 32));
            float E = ex2f((lo + hi) * 14.4269504088896340736f);  // exp(dot/0.1)
            if (diag && ml <= rl) E = 0.f;                         // strict upper tri
            rs0 = fmaf(E, wc[ml],       rs0);
            rs1 = fmaf(E, wc[128 + ml], rs1);
            rs2 = fmaf(E, wc[256 + ml], rs2);
        }
        lacc[0] = fmaf(w0r, rs0, lacc[0]);
        lacc[1] = fmaf(w0r, rs1, lacc[1]);
        lacc[2] = fmaf(w0r, rs2, lacc[2]);
        lacc[3] = fmaf(w1r, rs0, lacc[3]);
        lacc[4] = fmaf(w1r, rs1, lacc[4]);
        lacc[5] = fmaf(w1r, rs2, lacc[5]);
        lacc[6] = fmaf(w2r, rs0, lacc[6]);
        lacc[7] = fmaf(w2r, rs1, lacc[7]);
        lacc[8] = fmaf(w2r, rs2, lacc[8]);
    }

#pragma unroll
    for (int o = 16; o; o >>= 1)
#pragma unroll
        for (int q = 0; q < 9; q++)
            lacc[q] += __shfl_down_sync(0xffffffffu, lacc[q], o);

    __shared__ float rsum[16][9];
    int w = tid >> 5, l = tid & 31;
    if (l == 0)
#pragma unroll
        for (int q = 0; q < 9; q++) rsum[w][q] = lacc[q];
    __syncthreads();
    if (tid < 9) {
        float s = 0.f;
#pragma unroll
        for (int w2 = 0; w2 < 16; w2++) s += rsum[w2][tid];
        g_gpart[gid * 9 + tid] = s;
    }
}

// ================= finalize =================
__device__ double pair_loss(double S, double cnt, bool positive) {
    if (!(cnt > 0.0)) return 0.0;
    double mean = S / (cnt < 1.0 ? 1.0 : cnt);
    return positive ? -log(mean + 1e-6) : log1p(mean);
}

__global__ void __launch_bounds__(256)
finalize_kernel(const float* __restrict__ logits,
                const int* __restrict__ labels,
                float* __restrict__ out) {
    int tid = threadIdx.x;
    __shared__ double sred[256];
    __shared__ double sdice[2][9];
    __shared__ double sgp[6][9];
    __shared__ int    scnt[18];

    for (int b = 0; b < 2; b++) {
        double a[9];
#pragma unroll
        for (int q = 0; q < 9; q++) a[q] = 0.0;
        for (int i = b * 1024 + tid; i < (b + 1) * 1024; i += 256)
#pragma unroll
            for (int q = 0; q < 9; q++) a[q] += (double)g_dpart[i * 9 + q];
        for (int q = 0; q < 9; q++) {
            sred[tid] = a[q];
            __syncthreads();
            for (int s = 128; s; s >>= 1) {
                if (tid < s) sred[tid] += sred[tid + s];
                __syncthreads();
            }
            if (tid == 0) sdice[b][q] = sred[0];
            __syncthreads();
        }
    }

    if (tid < 32) {
        const int gs[7] = { 0, 528, 1056, 1066, 1076, 1077, 1078 };
        for (int g = 0; g < 6; g++) {
            double v[9];
#pragma unroll
            for (int q = 0; q < 9; q++) v[q] = 0.0;
            for (int i = gs[g] + tid; i < gs[g + 1]; i += 32)
#pragma unroll
                for (int q = 0; q < 9; q++) v[q] += (double)g_gpart[i * 9 + q];
#pragma unroll
            for (int q = 0; q < 9; q++)
                for (int o = 16; o; o >>= 1)
                    v[q] += __shfl_down_sync(0xffffffffu, v[q], o);
            if (tid == 0)
#pragma unroll
                for (int q = 0; q < 9; q++) sgp[g][q] = v[q];
        }
    } else if (tid < 64) {
        int l = tid - 32;
        int c[18];
#pragma unroll
        for (int k = 0; k < 18; k++) c[k] = 0;
        for (int i = l; i < 2 * NPOS; i += 32) {
            int cls = g_cls[i];
            if (cls > 2) continue;
            int b = i / NPOS, idx = i % NPOS;
            int sc = idx < 4096 ? 0 : (idx < 4608 ? 1 : 2);
            c[(b * 3 + sc) * 3 + cls]++;
        }
#pragma unroll
        for (int k = 0; k < 18; k++)
            for (int o = 16; o; o >>= 1)
                c[k] += __shfl_down_sync(0xffffffffu, c[k], o);
        if (l == 0)
#pragma unroll
            for (int k = 0; k < 18; k++) scnt[k] = c[k];
    }
    __syncthreads();

    if (tid == 0) {
        double dsum = 0.0;
        for (int b = 0; b < 2; b++)
            for (int c = 1; c < 3; c++) {
                double inter = sdice[b][c];
                double psum  = sdice[b][3 + c];
                double vcnt  = sdice[b][6 + c];
                dsum += (2.0 * inter + 1e-5) / (psum + vcnt + 1e-5);
            }
        double dice = 1.0 - dsum / 4.0;

        double fsum = 0.0;
        for (int i = 0; i < 6; i++) {
            double x  = (double)logits[i];
            double pt = 1.0 / (1.0 + exp(-x));
            if (labels[i] != 1) pt = 1.0 - pt;
            double om = 1.0 - pt;
            fsum += -0.25 * om * om * log(pt + 1e-6);
        }
        double focal = fsum / 6.0;

        const double wsc[3] = { 1.0, 0.8, 0.6 };
        double contr = 0.0;
        for (int sc = 0; sc < 3; sc++) {
            double sl = 0.0;
            for (int b = 0; b < 2; b++) {
                const double* T = sgp[sc * 2 + b];
                const int* cc = scnt + (b * 3 + sc) * 3;
                double c0 = cc[0], c1 = cc[1], c2 = cc[2];
                sl += pair_loss(2.0 * T[4],  c1 * c1 - c1, true);
                sl += pair_loss(2.0 * T[8],  c2 * c2 - c2, true);
                sl += pair_loss(T[5] + T[7], c1 * c2,      false);
                sl += pair_loss(T[1] + T[3], c0 * c1,      false);
                sl += pair_loss(T[2] + T[6], c0 * c2,      false);
            }
            contr += wsc[sc] * (sl * 0.5);
        }

        double total = dice + focal + 0.1 * contr;
        out[0] = (float)total;
        out[1] = (float)dice;
        out[2] = (float)focal;
        out[3] = (float)contr;
    }
}

// ================= launcher =================
extern "C" void kernel_launch(void* const* d_in, const int* in_sizes, int n_in,
                              void* d_out, int out_size) {
    const float* pred   = (const float*)d_in[0];
    const int*   tgt    = (const int*)d_in[1];
    const float* f0     = (const float*)d_in[2];
    const float* f1     = (const float*)d_in[3];
    const float* f2     = (const float*)d_in[4];
    const float* logits = (const float*)d_in[5];
    const int*   labels = (const int*)d_in[6];
    float*       out    = (float*)d_out;

    const int smemBytes = (128 * 48 + 128 * BSTRIDE + 6 * 128) * sizeof(float);
    cudaFuncSetAttribute(gram_kernel,
                         cudaFuncAttributeMaxDynamicSharedMemorySize, smemBytes);

    diceprep_kernel<<<NDICE + 37, 256>>>(pred, tgt, f0, f1, f2);
    gram_kernel<<<NGRAM, 512, smemBytes>>>();
    finalize_kernel<<<1, 256>>>(logits, labels, out);
}

// round 7
// speedup vs baseline: 1.0608x; 1.0608x over previous
#include <cuda_runtime.h>
#include <math.h>

// ---------------- constants ----------------
#define VOX   2097152          // 128^3
#define CCH   48               // feature channels
#define NPOS  4736             // 4096 + 512 + 128(pad) positions per batch
#define NGRAM 1078             // 2*528 + 2*10 + 2*1 gram tiles
#define NDICE 2048

// ---------------- device scratch ----------------
__device__ float g_dpart[NDICE * 9];      // dice per-block partials
__device__ float g_gpart[NGRAM * 9];      // gram per-block partials
__device__ float g_fnorm[2 * NPOS * CCH];
__device__ int   g_cls[2 * NPOS];

// ================= kernel A: fused dice + prep =================
__global__ void __launch_bounds__(256)
diceprep_kernel(const float* __restrict__ pred, const int* __restrict__ tgt,
                const float* __restrict__ f0, const float* __restrict__ f1,
                const float* __restrict__ f2) {
    int bid = blockIdx.x;
    if (bid < NDICE) {
        const int b = bid >> 10;
        const int chunk = bid & 1023;
        const int Q = VOX / 4;
        float fi0 = 0.f, fi1 = 0.f, fi2 = 0.f;
        float fp0 = 0.f, fp1 = 0.f, fp2 = 0.f;
        float fc0 = 0.f, fc1 = 0.f, fc2 = 0.f;
        const float4* P  = (const float4*)pred;
        const int4*   T4 = (const int4*)tgt;

        for (int q = chunk * 256 + threadIdx.x; q < Q; q += 1024 * 256) {
            float4 x0 = P[(size_t)(b * 3 + 0) * Q + q];
            float4 x1 = P[(size_t)(b * 3 + 1) * Q + q];
            float4 x2 = P[(size_t)(b * 3 + 2) * Q + q];
            int4   tv = T4[(size_t)b * Q + q];

#define DO_VOXEL(pa, pb, pc, tt)                                           \
            {                                                              \
                float e0 = __expf(pa);                                     \
                float e1 = __expf(pb);                                     \
                float e2 = __expf(pc);                                     \
                float inv = __fdividef(1.f, e0 + e1 + e2);                 \
                e0 *= inv; e1 *= inv; e2 *= inv;                           \
                fp0 += e0; fp1 += e1; fp2 += e2;                           \
                int tc = (tt) < 0 ? 0 : (tt);                              \
                if (tc == 0)      { fi0 += e0; fc0 += 1.f; }               \
                else if (tc == 1) { fi1 += e1; fc1 += 1.f; }               \
                else              { fi2 += e2; fc2 += 1.f; }               \
            }
            DO_VOXEL(x0.x, x1.x, x2.x, tv.x);
            DO_VOXEL(x0.y, x1.y, x2.y, tv.y);
            DO_VOXEL(x0.z, x1.z, x2.z, tv.z);
            DO_VOXEL(x0.w, x1.w, x2.w, tv.w);
#undef DO_VOXEL
        }

        float v[9] = { fi0, fi1, fi2, fp0, fp1, fp2, fc0, fc1, fc2 };
#pragma unroll
        for (int o = 16; o; o >>= 1)
#pragma unroll
            for (int q = 0; q < 9; q++)
                v[q] += __shfl_down_sync(0xffffffffu, v[q], o);

        __shared__ float red[8][9];
        int w = threadIdx.x >> 5, l = threadIdx.x & 31;
        if (l == 0)
#pragma unroll
            for (int q = 0; q < 9; q++) red[w][q] = v[q];
        __syncthreads();
        if (threadIdx.x < 9) {
            float s = 0.f;
#pragma unroll
            for (int w2 = 0; w2 < 8; w2++) s += red[w2][threadIdx.x];
            g_dpart[bid * 9 + threadIdx.x] = s;
        }
    } else {
        int gid = (bid - NDICE) * 256 + threadIdx.x;
        if (gid >= 2 * NPOS) return;
        int b = gid / NPOS, idx = gid % NPOS;
        const float* fmap;
        int D, s, N, n;
        if (idx < 4096)      { fmap = f0; D = 16; s = 8;  N = 4096; n = idx; }
        else if (idx < 4608) { fmap = f1; D = 8;  s = 16; N = 512;  n = idx - 4096; }
        else                 { fmap = f2; D = 4;  s = 32; N = 64;   n = idx - 4608; }

        float4* dst = (float4*)(g_fnorm + (size_t)gid * CCH);
        if (n >= N) {
            float4 z = make_float4(0.f, 0.f, 0.f, 0.f);
#pragma unroll
            for (int c = 0; c < CCH / 4; c++) dst[c] = z;
            g_cls[gid] = 3;
            return;
        }
        int z = n / (D * D), y = (n / D) % D, x = n % D;
        int tv = tgt[(size_t)b * VOX + ((size_t)(z * s) * 128 + y * s) * 128 + x * s];
        int cls = tv < 0 ? 0 : (tv > 2 ? 2 : tv);
        g_cls[gid] = cls;

        float v[CCH];
        float ss = 0.f;
#pragma unroll
        for (int c = 0; c < CCH; c++) {
            v[c] = fmap[((size_t)b * CCH + c) * N + n];
            ss = fmaf(v[c], v[c], ss);
        }
        float inv = 1.f / fmaxf(sqrtf(ss), 1e-12f);
#pragma unroll
        for (int c = 0; c < CCH / 4; c++)
            dst[c] = make_float4(v[4 * c] * inv, v[4 * c + 1] * inv,
                                 v[4 * c + 2] * inv, v[4 * c + 3] * inv);
    }
}

// ---------------- helpers ----------------
__device__ __forceinline__ float ex2f(float x) {
    float y;
    asm("ex2.approx.f32 %0, %1;" : "=f"(y) : "f"(x));
    return y;
}

// ====== kernel B: gram, scalar FFMA, 256 thr, 8x8, reg-budgeted ======
#define BSTRIDE 52
__global__ void __launch_bounds__(256, 1)
gram_kernel() {
    int gid = blockIdx.x;
    int b, p, T, off;
    if (gid < 1056)      { b = gid / 528;  p = gid % 528; T = 32; off = 0; }
    else if (gid < 1076) { int l = gid - 1056; b = l / 10; p = l % 10; T = 4; off = 4096; }
    else                 { b = gid - 1076; p = 0; T = 1; off = 4608; }
    int by = 0;
    while (p >= T - by) { p -= T - by; by++; }
    int bx = by + p;

    extern __shared__ float sm[];
    float* As = sm;                          // [128][48]
    float* Bs = sm + 128 * 48;               // [128][BSTRIDE]
    float* wr = Bs + 128 * BSTRIDE;          // [3][128]
    float* wc = wr + 3 * 128;                // [3][128]

    int tid = threadIdx.x;
    const float4* FR4 = (const float4*)(g_fnorm + ((size_t)b * NPOS + off + by * 128) * CCH);
    const float4* FC4 = (const float4*)(g_fnorm + ((size_t)b * NPOS + off + bx * 128) * CCH);

    for (int t = tid; t < 128 * 12; t += 256)
        ((float4*)As)[t] = FR4[t];
    for (int t = tid; t < 128 * 12; t += 256) {
        int r = t / 12, kq = t % 12;
        *(float4*)(Bs + r * BSTRIDE + kq * 4) = FC4[t];   // 52%4==0 -> aligned
    }
    if (tid < 128) {
        int cr = g_cls[b * NPOS + off + by * 128 + tid];
        wr[tid]       = (cr == 0) ? 1.f : 0.f;
        wr[128 + tid] = (cr == 1) ? 1.f : 0.f;
        wr[256 + tid] = (cr == 2) ? 1.f : 0.f;
    } else {
        int t2 = tid - 128;
        int cc = g_cls[b * NPOS + off + bx * 128 + t2];
        wc[t2]       = (cc == 0) ? 1.f : 0.f;
        wc[128 + t2] = (cc == 1) ? 1.f : 0.f;
        wc[256 + t2] = (cc == 2) ? 1.f : 0.f;
    }
    __syncthreads();

    int ty = tid >> 4, tx = tid & 15;
    // rows: ty*8 + i (contiguous per thread), cols: tx + j*16

    float acc[8][8];
#pragma unroll
    for (int i = 0; i < 8; i++)
#pragma unroll
        for (int j = 0; j < 8; j++) acc[i][j] = 0.f;

#pragma unroll 1
    for (int kc = 0; kc < 12; kc++) {
        float4 a4[8];
#pragma unroll
        for (int i = 0; i < 8; i++)
            a4[i] = *(const float4*)(As + (ty * 8 + i) * 48 + kc * 4);
#pragma unroll
        for (int j = 0; j < 8; j++) {
            float4 b4 = *(const float4*)(Bs + (tx + j * 16) * BSTRIDE + kc * 4);
#pragma unroll
            for (int i = 0; i < 8; i++) {
                acc[i][j] = fmaf(a4[i].x, b4.x, acc[i][j]);
                acc[i][j] = fmaf(a4[i].y, b4.y, acc[i][j]);
                acc[i][j] = fmaf(a4[i].z, b4.z, acc[i][j]);
                acc[i][j] = fmaf(a4[i].w, b4.w, acc[i][j]);
            }
        }
    }

    // hoist column one-hot weights (24 regs; a4 now dead)
    float wc0[8], wc1[8], wc2[8];
#pragma unroll
    for (int j = 0; j < 8; j++) {
        int ml = tx + j * 16;
        wc0[j] = wc[ml];
        wc1[j] = wc[128 + ml];
        wc2[j] = wc[256 + ml];
    }

    float lacc[9];
#pragma unroll
    for (int q = 0; q < 9; q++) lacc[q] = 0.f;

    bool diag = (by == bx);
#pragma unroll
    for (int i = 0; i < 8; i++) {
        int rl = ty * 8 + i;
        float w0r = wr[rl], w1r = wr[128 + rl], w2r = wr[256 + rl];
        float rs0 = 0.f, rs1 = 0.f, rs2 = 0.f;
#pragma unroll
        for (int j = 0; j < 8; j++) {
            int ml = tx + j * 16;
            float E = ex2f(acc[i][j] * 14.4269504088896340736f);  // exp(dot/0.1)
            if (diag && ml <= rl) E = 0.f;                         // strict upper tri
            rs0 = fmaf(E, wc0[j], rs0);
            rs1 = fmaf(E, wc1[j], rs1);
            rs2 = fmaf(E, wc2[j], rs2);
        }
        lacc[0] = fmaf(w0r, rs0, lacc[0]);
        lacc[1] = fmaf(w0r, rs1, lacc[1]);
        lacc[2] = fmaf(w0r, rs2, lacc[2]);
        lacc[3] = fmaf(w1r, rs0, lacc[3]);
        lacc[4] = fmaf(w1r, rs1, lacc[4]);
        lacc[5] = fmaf(w1r, rs2, lacc[5]);
        lacc[6] = fmaf(w2r, rs0, lacc[6]);
        lacc[7] = fmaf(w2r, rs1, lacc[7]);
        lacc[8] = fmaf(w2r, rs2, lacc[8]);
    }

#pragma unroll
    for (int o = 16; o; o >>= 1)
#pragma unroll
        for (int q = 0; q < 9; q++)
            lacc[q] += __shfl_down_sync(0xffffffffu, lacc[q], o);

    __shared__ float rsum[8][9];
    int w = tid >> 5, l = tid & 31;
    if (l == 0)
#pragma unroll
        for (int q = 0; q < 9; q++) rsum[w][q] = lacc[q];
    __syncthreads();
    if (tid < 9) {
        float s = 0.f;
#pragma unroll
        for (int w2 = 0; w2 < 8; w2++) s += rsum[w2][tid];
        g_gpart[gid * 9 + tid] = s;
    }
}

// ================= finalize =================
__device__ double pair_loss(double S, double cnt, bool positive) {
    if (!(cnt > 0.0)) return 0.0;
    double mean = S / (cnt < 1.0 ? 1.0 : cnt);
    return positive ? -log(mean + 1e-6) : log1p(mean);
}

__global__ void __launch_bounds__(256)
finalize_kernel(const float* __restrict__ logits,
                const int* __restrict__ labels,
                float* __restrict__ out) {
    int tid = threadIdx.x;
    __shared__ double sred[256];
    __shared__ double sdice[2][9];
    __shared__ double sgp[6][9];
    __shared__ int    scnt[18];

    for (int b = 0; b < 2; b++) {
        double a[9];
#pragma unroll
        for (int q = 0; q < 9; q++) a[q] = 0.0;
        for (int i = b * 1024 + tid; i < (b + 1) * 1024; i += 256)
#pragma unroll
            for (int q = 0; q < 9; q++) a[q] += (double)g_dpart[i * 9 + q];
        for (int q = 0; q < 9; q++) {
            sred[tid] = a[q];
            __syncthreads();
            for (int s = 128; s; s >>= 1) {
                if (tid < s) sred[tid] += sred[tid + s];
                __syncthreads();
            }
            if (tid == 0) sdice[b][q] = sred[0];
            __syncthreads();
        }
    }

    if (tid < 32) {
        const int gs[7] = { 0, 528, 1056, 1066, 1076, 1077, 1078 };
        for (int g = 0; g < 6; g++) {
            double v[9];
#pragma unroll
            for (int q = 0; q < 9; q++) v[q] = 0.0;
            for (int i = gs[g] + tid; i < gs[g + 1]; i += 32)
#pragma unroll
                for (int q = 0; q < 9; q++) v[q] += (double)g_gpart[i * 9 + q];
#pragma unroll
            for (int q = 0; q < 9; q++)
                for (int o = 16; o; o >>= 1)
                    v[q] += __shfl_down_sync(0xffffffffu, v[q], o);
            if (tid == 0)
#pragma unroll
                for (int q = 0; q < 9; q++) sgp[g][q] = v[q];
        }
    } else if (tid < 64) {
        int l = tid - 32;
        int c[18];
#pragma unroll
        for (int k = 0; k < 18; k++) c[k] = 0;
        for (int i = l; i < 2 * NPOS; i += 32) {
            int cls = g_cls[i];
            if (cls > 2) continue;
            int b = i / NPOS, idx = i % NPOS;
            int sc = idx < 4096 ? 0 : (idx < 4608 ? 1 : 2);
            c[(b * 3 + sc) * 3 + cls]++;
        }
#pragma unroll
        for (int k = 0; k < 18; k++)
            for (int o = 16; o; o >>= 1)
                c[k] += __shfl_down_sync(0xffffffffu, c[k], o);
        if (l == 0)
#pragma unroll
            for (int k = 0; k < 18; k++) scnt[k] = c[k];
    }
    __syncthreads();

    if (tid == 0) {
        double dsum = 0.0;
        for (int b = 0; b < 2; b++)
            for (int c = 1; c < 3; c++) {
                double inter = sdice[b][c];
                double psum  = sdice[b][3 + c];
                double vcnt  = sdice[b][6 + c];
                dsum += (2.0 * inter + 1e-5) / (psum + vcnt + 1e-5);
            }
        double dice = 1.0 - dsum / 4.0;

        double fsum = 0.0;
        for (int i = 0; i < 6; i++) {
            double x  = (double)logits[i];
            double pt = 1.0 / (1.0 + exp(-x));
            if (labels[i] != 1) pt = 1.0 - pt;
            double om = 1.0 - pt;
            fsum += -0.25 * om * om * log(pt + 1e-6);
        }
        double focal = fsum / 6.0;

        const double wsc[3] = { 1.0, 0.8, 0.6 };
        double contr = 0.0;
        for (int sc = 0; sc < 3; sc++) {
            double sl = 0.0;
            for (int b = 0; b < 2; b++) {
                const double* T = sgp[sc * 2 + b];
                const int* cc = scnt + (b * 3 + sc) * 3;
                double c0 = cc[0], c1 = cc[1], c2 = cc[2];
                sl += pair_loss(2.0 * T[4],  c1 * c1 - c1, true);
                sl += pair_loss(2.0 * T[8],  c2 * c2 - c2, true);
                sl += pair_loss(T[5] + T[7], c1 * c2,      false);
                sl += pair_loss(T[1] + T[3], c0 * c1,      false);
                sl += pair_loss(T[2] + T[6], c0 * c2,      false);
            }
            contr += wsc[sc] * (sl * 0.5);
        }

        double total = dice + focal + 0.1 * contr;
        out[0] = (float)total;
        out[1] = (float)dice;
        out[2] = (float)focal;
        out[3] = (float)contr;
    }
}

// ================= launcher =================
extern "C" void kernel_launch(void* const* d_in, const int* in_sizes, int n_in,
                              void* d_out, int out_size) {
    const float* pred   = (const float*)d_in[0];
    const int*   tgt    = (const int*)d_in[1];
    const float* f0     = (const float*)d_in[2];
    const float* f1     = (const float*)d_in[3];
    const float* f2     = (const float*)d_in[4];
    const float* logits = (const float*)d_in[5];
    const int*   labels = (const int*)d_in[6];
    float*       out    = (float*)d_out;

    const int smemBytes = (128 * 48 + 128 * BSTRIDE + 6 * 128) * sizeof(float);
    cudaFuncSetAttribute(gram_kernel,
                         cudaFuncAttributeMaxDynamicSharedMemorySize, smemBytes);

    diceprep_kernel<<<NDICE + 37, 256>>>(pred, tgt, f0, f1, f2);
    gram_kernel<<<NGRAM, 256, smemBytes>>>();
    finalize_kernel<<<1, 256>>>(logits, labels, out);
}